// round 4
// baseline (speedup 1.0000x reference)
#include <cuda_runtime.h>
#include <cuda_bf16.h>
#include <cstdint>

// Problem shape
#define T_TOK   32
#define K_IN    4096
#define N_OUT   14336

// GEMM tiling
#define O_TILE  256          // outputs per block
#define KC      16           // K-chunk staged in SMEM
#define TPB     128          // threads per block
#define KSPLIT  8            // K split across grid.y
#define KPER    (K_IN / KSPLIT)   // 512
#define WPAD    260          // padded row stride (floats) for w_s, 16B-aligned rows

// Scratch (device globals: no allocation allowed in kernel_launch)
__device__ float g_xs[K_IN * T_TOK];                    // xs transposed: [i][t]
__device__ float g_part[KSPLIT * T_TOK * N_OUT];        // K-split partials

// ---------------------------------------------------------------------------
// Kernel 1: xs[i][t] = x[t][i] * scales[i]
// ---------------------------------------------------------------------------
__global__ void prep_kernel(const float* __restrict__ x,
                            const float* __restrict__ scales) {
    int idx = blockIdx.x * blockDim.x + threadIdx.x;   // 0 .. 131071
    int i = idx >> 5;
    int t = idx & 31;
    g_xs[idx] = x[t * K_IN + i] * scales[i];
}

// packed fp32x2 FMA (FFMA2) — PTX-only form, doubles fp32 throughput on sm_103a
__device__ __forceinline__ void fma2(float2& d, float2 a, float2 b) {
    unsigned long long da = *reinterpret_cast<unsigned long long*>(&a);
    unsigned long long db = *reinterpret_cast<unsigned long long*>(&b);
    unsigned long long dd = *reinterpret_cast<unsigned long long*>(&d);
    asm("fma.rn.f32x2 %0, %1, %2, %3;" : "=l"(dd) : "l"(da), "l"(db), "l"(dd));
    d = *reinterpret_cast<float2*>(&dd);
}

// int8-valued int32 -> fp32 without I2F: exponent-bias trick (exact for |v|<2^22)
__device__ __forceinline__ float i2f_fast(int v) {
    return __int_as_float(v + 0x4B400000) - 12582912.0f;
}

// ---------------------------------------------------------------------------
// Kernel 2: tiled GEMM. block = (o-tile 256) x (all 32 tokens) x (K slice 512)
// thread tile = 8 o x 8 t  (32 f32x2 accumulators)
// thread map: og = tid/4 (32 groups of 8 o), tg = tid%4 (4 groups of 8 t)
// ---------------------------------------------------------------------------
__global__ __launch_bounds__(TPB) void gemm_kernel(const int* __restrict__ w) {
    __shared__ float w_s[KC * WPAD];        // [k][o] padded
    __shared__ float xs_s[KC * T_TOK];      // [k][t]

    const int tid = threadIdx.x;
    const int o0  = blockIdx.x * O_TILE;
    const int ks  = blockIdx.y;
    const int kbase = ks * KPER;

    const int og = tid >> 2;   // 0..31
    const int tg = tid & 3;    // 0..3

    float2 acc[8][4];
    #pragma unroll
    for (int a = 0; a < 8; a++)
        #pragma unroll
        for (int b = 0; b < 4; b++) acc[a][b] = make_float2(0.f, 0.f);

    for (int kc = 0; kc < KPER / KC; kc++) {
        const int k0 = kbase + kc * KC;

        // ---- stage W tile: 256 rows x 16 ints, converted to fp32, transposed [k][o]
        #pragma unroll
        for (int pass = 0; pass < 8; pass++) {
            int idx = pass * TPB + tid;       // 0..1023
            int row = idx >> 2;               // 0..255
            int seg = idx & 3;                // 0..3 (4 ints each)
            const int4 v = *reinterpret_cast<const int4*>(
                &w[(size_t)(o0 + row) * K_IN + k0 + seg * 4]);
            w_s[(seg * 4 + 0) * WPAD + row] = i2f_fast(v.x);
            w_s[(seg * 4 + 1) * WPAD + row] = i2f_fast(v.y);
            w_s[(seg * 4 + 2) * WPAD + row] = i2f_fast(v.z);
            w_s[(seg * 4 + 3) * WPAD + row] = i2f_fast(v.w);
        }
        // ---- stage xs chunk: 16 k x 32 t = 512 floats
        {
            const float4 v = *reinterpret_cast<const float4*>(&g_xs[k0 * T_TOK + tid * 4]);
            *reinterpret_cast<float4*>(&xs_s[tid * 4]) = v;
        }
        __syncthreads();

        // ---- compute
        #pragma unroll
        for (int k = 0; k < KC; k++) {
            const float4 wa = *reinterpret_cast<const float4*>(&w_s[k * WPAD + og * 8 + 0]);
            const float4 wb = *reinterpret_cast<const float4*>(&w_s[k * WPAD + og * 8 + 4]);
            const float4 xa = *reinterpret_cast<const float4*>(&xs_s[k * T_TOK + tg * 8 + 0]);
            const float4 xb = *reinterpret_cast<const float4*>(&xs_s[k * T_TOK + tg * 8 + 4]);
            const float w8[8] = {wa.x, wa.y, wa.z, wa.w, wb.x, wb.y, wb.z, wb.w};
            float2 xv[4];
            xv[0] = make_float2(xa.x, xa.y);
            xv[1] = make_float2(xa.z, xa.w);
            xv[2] = make_float2(xb.x, xb.y);
            xv[3] = make_float2(xb.z, xb.w);
            #pragma unroll
            for (int oi = 0; oi < 8; oi++) {
                const float2 wv = make_float2(w8[oi], w8[oi]);
                #pragma unroll
                for (int tj = 0; tj < 4; tj++) fma2(acc[oi][tj], wv, xv[tj]);
            }
        }
        __syncthreads();
    }

    // ---- epilogue: stage through SMEM (reuse w_s) in 4 token-quarters for
    //      coalesced partial writes: part[ks][t][o]
    for (int q = 0; q < 4; q++) {
        if (tg == q) {
            #pragma unroll
            for (int oi = 0; oi < 8; oi++)
                #pragma unroll
                for (int tj = 0; tj < 4; tj++) {
                    w_s[(2 * tj + 0) * WPAD + og * 8 + oi] = acc[oi][tj].x;
                    w_s[(2 * tj + 1) * WPAD + og * 8 + oi] = acc[oi][tj].y;
                }
        }
        __syncthreads();
        // copy 8 rows x 256 cols to gmem
        for (int idx = tid; idx < 8 * O_TILE; idx += TPB) {
            int tt  = idx >> 8;          // 0..7
            int col = idx & 255;
            int t   = q * 8 + tt;
            g_part[((size_t)ks * T_TOK + t) * N_OUT + o0 + col] = w_s[tt * WPAD + col];
        }
        __syncthreads();
    }
}

// ---------------------------------------------------------------------------
// Kernel 3: reduce K-split partials into d_out
// ---------------------------------------------------------------------------
__global__ void reduce_kernel(float* __restrict__ out) {
    int idx = blockIdx.x * blockDim.x + threadIdx.x;   // 0 .. 458751
    float s = 0.f;
    #pragma unroll
    for (int ks = 0; ks < KSPLIT; ks++)
        s += g_part[(size_t)ks * T_TOK * N_OUT + idx];
    out[idx] = s;
}

extern "C" void kernel_launch(void* const* d_in, const int* in_sizes, int n_in,
                              void* d_out, int out_size) {
    const float* x      = (const float*)d_in[0];
    const int*   weight = (const int*)d_in[1];
    const float* scales = (const float*)d_in[2];
    float* out = (float*)d_out;

    prep_kernel<<<(K_IN * T_TOK) / 512, 512>>>(x, scales);
    dim3 grid(N_OUT / O_TILE, KSPLIT);     // 56 x 8 = 448 blocks
    gemm_kernel<<<grid, TPB>>>(weight);
    reduce_kernel<<<(T_TOK * N_OUT) / 256, 256>>>(out);
}